// round 2
// baseline (speedup 1.0000x reference)
#include <cuda_runtime.h>
#include <cuda_bf16.h>
#include <cstdint>

// Problem constants
#define BATCH     8
#define NTOK      8192          // B*N
#define DDIM      3
#define CDIM      64
#define BAS       16
#define U_IN      512
#define U_EQ      64
#define FDIM      8192          // 2*C*C
#define NCOLS     2560          // 512 + 1024 + 1024
#define EQW       2048          // per-token wl width (2 heads x 1024)

// Scratch (device globals: allocation-free rule)
__device__ float g_feats[(size_t)NTOK * FDIM];   // 256 MB, tf32-rounded values
__device__ float g_wl[(size_t)NTOK * EQW];       // 64 MB, post BN+ReLU eq activations

__device__ __forceinline__ float to_tf32(float x) {
    uint32_t r;
    asm("cvt.rna.tf32.f32 %0, %1;" : "=r"(r) : "f"(x));
    return __uint_as_float(r);
}

__device__ __forceinline__ void mma_tf32(float* d, const uint32_t* a, const uint32_t* b) {
    asm volatile(
        "mma.sync.aligned.m16n8k8.row.col.f32.tf32.tf32.f32 "
        "{%0,%1,%2,%3}, {%4,%5,%6,%7}, {%8,%9}, {%0,%1,%2,%3};\n"
        : "+f"(d[0]), "+f"(d[1]), "+f"(d[2]), "+f"(d[3])
        : "r"(a[0]), "r"(a[1]), "r"(a[2]), "r"(a[3]),
          "r"(b[0]), "r"(b[1]));
}

// ---------------------------------------------------------------------------
// Kernel 1: feats[tok, h*4096 + i*64 + j] = sum_d t[d,i] * l2norm(u)[d,j]
// One block per token, 128 threads (one per (h,i)).
// ---------------------------------------------------------------------------
__global__ void feats_kernel(const float* __restrict__ t1, const float* __restrict__ t2,
                             const float* __restrict__ u1, const float* __restrict__ u2) {
    const int tok = blockIdx.x;
    const int tid = threadIdx.x;
    __shared__ float s_t[384];   // [h][d][i] = h*192 + d*64 + i
    __shared__ float s_u[384];

    const size_t base = (size_t)tok * 192;
    for (int idx = tid; idx < 192; idx += 128) {
        s_t[idx]       = t1[base + idx];
        s_t[192 + idx] = t2[base + idx];
        s_u[idx]       = u1[base + idx];
        s_u[192 + idx] = u2[base + idx];
    }
    __syncthreads();

    {   // l2-normalize u columns (axis = D): 128 threads = 128 (h,j) columns
        const int h = tid >> 6, j = tid & 63;
        float* u = s_u + h * 192;
        float a = u[j], b = u[64 + j], c = u[128 + j];
        float inv = rsqrtf(fmaxf(a * a + b * b + c * c, 0.01f));
        u[j] = a * inv; u[64 + j] = b * inv; u[128 + j] = c * inv;
    }
    __syncthreads();

    const int h = tid >> 6, i = tid & 63;
    const float* tt = s_t + h * 192;
    const float* uu = s_u + h * 192;
    const float ta = tt[i], tb = tt[64 + i], tc = tt[128 + i];
    float* dst = g_feats + (size_t)tok * FDIM + h * 4096 + i * 64;

    #pragma unroll
    for (int j0 = 0; j0 < 64; j0 += 4) {
        float4 v;
        v.x = to_tf32(fmaf(ta, uu[j0 + 0], fmaf(tb, uu[64 + j0 + 0], tc * uu[128 + j0 + 0])));
        v.y = to_tf32(fmaf(ta, uu[j0 + 1], fmaf(tb, uu[64 + j0 + 1], tc * uu[128 + j0 + 1])));
        v.z = to_tf32(fmaf(ta, uu[j0 + 2], fmaf(tb, uu[64 + j0 + 2], tc * uu[128 + j0 + 2])));
        v.w = to_tf32(fmaf(ta, uu[j0 + 3], fmaf(tb, uu[64 + j0 + 3], tc * uu[128 + j0 + 3])));
        *(float4*)(dst + j0) = v;
    }
}

// ---------------------------------------------------------------------------
// Kernel 2: C = feats @ [W_inv | W_eq0 | W_eq1], fused bias + BN + ReLU.
// 128x128x16 tiles, tf32 mma.sync m16n8k8, 8 warps (2x4), warp tile 64x32.
// K-major smem with 136-float rows: conflict-free frag loads & transpose STS.
// Grid: x = N-tile (fast, keeps weights L2-resident), y = M-tile.
// ---------------------------------------------------------------------------
#define SROW 136
#define KT_ITERS (FDIM / 16)

__global__ __launch_bounds__(256, 2) void gemm_kernel(
    const float* __restrict__ Winv, const float* __restrict__ Weq,
    const float* __restrict__ b_inv, const float* __restrict__ g_inv, const float* __restrict__ be_inv,
    const float* __restrict__ b_eq,  const float* __restrict__ g_eq,  const float* __restrict__ be_eq,
    float* __restrict__ out_invar)
{
    __shared__ float sA[2][16 * SROW];   // [k][m]
    __shared__ float sB[2][16 * SROW];   // [k][n]
    __shared__ float s_bias[128], s_gam[128], s_bet[128];

    const int tid = threadIdx.x;
    const int bn = blockIdx.x;           // 0..19
    const int bm = blockIdx.y;           // 0..63
    const int colBase = bn * 128;

    const float* Bsrc; int ldb;
    if (bn < 4)       { Bsrc = Winv + colBase;                         ldb = 512;  }
    else if (bn < 12) { Bsrc = Weq + (colBase - 512);                  ldb = 1024; }
    else              { Bsrc = Weq + (size_t)FDIM * 1024 + (colBase - 1536); ldb = 1024; }

    if (tid < 128) {
        int c = colBase + tid;
        if (c < 512) { s_bias[tid] = b_inv[c]; s_gam[tid] = g_inv[c]; s_bet[tid] = be_inv[c]; }
        else { int j = c - 512; s_bias[tid] = b_eq[j]; s_gam[tid] = g_eq[j]; s_bet[tid] = be_eq[j]; }
    }

    // A load mapping: thread -> (row = tid>>2 and +64, k-quad = tid&3)
    const int arow = tid >> 2;
    const int akq  = tid & 3;
    const float* Aptr = g_feats + (size_t)(bm * 128 + arow) * FDIM + akq * 4;
    // B load mapping: thread -> (k = tid>>4, n-quad = tid&15 and +16)
    const int bk  = tid >> 4;
    const int bnq = tid & 15;
    const float* Bptr = Bsrc + (size_t)bk * ldb + bnq * 4;

    float4 ra0, ra1, rb0, rb1;
    auto ldgTile = [&](int kt) {
        const float* a = Aptr + kt * 16;
        ra0 = *(const float4*)(a);
        ra1 = *(const float4*)(a + (size_t)64 * FDIM);
        const float* b = Bptr + (size_t)kt * 16 * ldb;
        rb0 = *(const float4*)(b);
        rb1 = *(const float4*)(b + 64);
    };
    auto stsTile = [&](int buf) {
        float* A_s = sA[buf]; float* B_s = sB[buf];
        A_s[(akq * 4 + 0) * SROW + arow] = ra0.x;
        A_s[(akq * 4 + 1) * SROW + arow] = ra0.y;
        A_s[(akq * 4 + 2) * SROW + arow] = ra0.z;
        A_s[(akq * 4 + 3) * SROW + arow] = ra0.w;
        A_s[(akq * 4 + 0) * SROW + arow + 64] = ra1.x;
        A_s[(akq * 4 + 1) * SROW + arow + 64] = ra1.y;
        A_s[(akq * 4 + 2) * SROW + arow + 64] = ra1.z;
        A_s[(akq * 4 + 3) * SROW + arow + 64] = ra1.w;
        float4 c0, c1;
        c0.x = to_tf32(rb0.x); c0.y = to_tf32(rb0.y); c0.z = to_tf32(rb0.z); c0.w = to_tf32(rb0.w);
        c1.x = to_tf32(rb1.x); c1.y = to_tf32(rb1.y); c1.z = to_tf32(rb1.z); c1.w = to_tf32(rb1.w);
        *(float4*)&B_s[bk * SROW + bnq * 4]      = c0;
        *(float4*)&B_s[bk * SROW + 64 + bnq * 4] = c1;
    };

    const int wid = tid >> 5, lane = tid & 31;
    const int mBase = (wid >> 2) * 64;
    const int nBase = (wid & 3) * 32;
    const int gID = lane >> 2, tig = lane & 3;

    float acc[4][4][4];
    #pragma unroll
    for (int a = 0; a < 4; a++)
        #pragma unroll
        for (int b = 0; b < 4; b++)
            #pragma unroll
            for (int c = 0; c < 4; c++) acc[a][b][c] = 0.f;

    auto compute = [&](int buf) {
        const float* A_s = sA[buf]; const float* B_s = sB[buf];
        #pragma unroll
        for (int k8 = 0; k8 < 2; k8++) {
            const int kk = k8 * 8;
            uint32_t af[4][4], bf[4][2];
            #pragma unroll
            for (int mt = 0; mt < 4; mt++) {
                int r = mBase + mt * 16 + gID;
                af[mt][0] = __float_as_uint(A_s[(kk + tig) * SROW + r]);
                af[mt][1] = __float_as_uint(A_s[(kk + tig) * SROW + r + 8]);
                af[mt][2] = __float_as_uint(A_s[(kk + 4 + tig) * SROW + r]);
                af[mt][3] = __float_as_uint(A_s[(kk + 4 + tig) * SROW + r + 8]);
            }
            #pragma unroll
            for (int nt = 0; nt < 4; nt++) {
                int c = nBase + nt * 8 + gID;
                bf[nt][0] = __float_as_uint(B_s[(kk + tig) * SROW + c]);
                bf[nt][1] = __float_as_uint(B_s[(kk + 4 + tig) * SROW + c]);
            }
            #pragma unroll
            for (int mt = 0; mt < 4; mt++)
                #pragma unroll
                for (int nt = 0; nt < 4; nt++)
                    mma_tf32(acc[mt][nt], af[mt], bf[nt]);
        }
    };

    ldgTile(0); stsTile(0); __syncthreads();
    int cur = 0;
    for (int kt = 0; kt < KT_ITERS; kt++) {
        const bool more = (kt + 1) < KT_ITERS;
        if (more) ldgTile(kt + 1);
        compute(cur);
        if (more) stsTile(cur ^ 1);
        __syncthreads();
        cur ^= 1;
    }

    // Epilogue: bias + inference BN (mean 0, var 1) + ReLU
    const float BNS = 0.99950037468777325f;   // 1/sqrt(1.001)
    const bool isInv = (bn < 4);
    #pragma unroll
    for (int mt = 0; mt < 4; mt++) {
        const int r0 = bm * 128 + mBase + mt * 16 + gID;
        #pragma unroll
        for (int nt = 0; nt < 4; nt++) {
            const int cl = nBase + nt * 8 + tig * 2;
            const float ga0 = s_gam[cl] * BNS,   ga1 = s_gam[cl + 1] * BNS;
            const float bi0 = s_bias[cl],        bi1 = s_bias[cl + 1];
            const float be0 = s_bet[cl],         be1 = s_bet[cl + 1];
            float v0 = fmaxf(fmaf(ga0, acc[mt][nt][0] + bi0, be0), 0.f);
            float v1 = fmaxf(fmaf(ga1, acc[mt][nt][1] + bi1, be1), 0.f);
            float v2 = fmaxf(fmaf(ga0, acc[mt][nt][2] + bi0, be0), 0.f);
            float v3 = fmaxf(fmaf(ga1, acc[mt][nt][3] + bi1, be1), 0.f);
            const int c = colBase + cl;
            if (isInv) {
                *(float2*)&out_invar[(size_t)r0 * U_IN + c]       = make_float2(v0, v1);
                *(float2*)&out_invar[(size_t)(r0 + 8) * U_IN + c] = make_float2(v2, v3);
            } else {
                const int cw = c - 512;
                *(float2*)&g_wl[(size_t)r0 * EQW + cw]       = make_float2(v0, v1);
                *(float2*)&g_wl[(size_t)(r0 + 8) * EQW + cw] = make_float2(v2, v3);
            }
        }
    }
}

// ---------------------------------------------------------------------------
// Kernel 3: eqvar[tok, m, l*64+i] = sum_j wl[tok, l*1024 + i*16 + j] * V_l[tok, m, j]
// One block per token, 384 threads (one per output element).
// ---------------------------------------------------------------------------
__global__ void recomb_kernel(const float* __restrict__ V1, const float* __restrict__ V2,
                              float* __restrict__ out_eq) {
    const int tok = blockIdx.x;
    const int tid = threadIdx.x;           // 0..383
    __shared__ float sV[96];               // [l][m][j] = l*48 + m*16 + j
    if (tid < 96) {
        int l = tid / 48, r = tid % 48;
        sV[tid] = (l ? V2 : V1)[(size_t)tok * 48 + r];
    }
    __syncthreads();

    const int m = tid >> 7;                // 0..2
    const int c = tid & 127;
    const int l = c >> 6, i = c & 63;
    const float* w = g_wl + (size_t)tok * EQW + l * 1024 + i * 16;
    const float* v = sV + l * 48 + m * 16;
    float s = 0.f;
    #pragma unroll
    for (int j = 0; j < 16; j++) s = fmaf(w[j], v[j], s);
    out_eq[(size_t)tok * 384 + m * 128 + c] = s;
}

// ---------------------------------------------------------------------------
extern "C" void kernel_launch(void* const* d_in, const int* in_sizes, int n_in,
                              void* d_out, int out_size) {
    const float* t1    = (const float*)d_in[0];
    const float* t2    = (const float*)d_in[1];
    const float* u1    = (const float*)d_in[2];
    const float* u2    = (const float*)d_in[3];
    const float* V1    = (const float*)d_in[4];
    const float* V2    = (const float*)d_in[5];
    const float* W_inv = (const float*)d_in[6];
    const float* b_inv = (const float*)d_in[7];
    const float* g_inv = (const float*)d_in[8];
    const float* be_inv= (const float*)d_in[9];
    const float* W_eq  = (const float*)d_in[10];
    const float* b_eq  = (const float*)d_in[11];
    const float* g_eq  = (const float*)d_in[12];
    const float* be_eq = (const float*)d_in[13];
    float* out = (float*)d_out;

    feats_kernel<<<NTOK, 128>>>(t1, t2, u1, u2);
    gemm_kernel<<<dim3(NCOLS / 128, NTOK / 128), 256>>>(
        W_inv, W_eq, b_inv, g_inv, be_inv, b_eq, g_eq, be_eq, out);
    recomb_kernel<<<NTOK, 384>>>(V1, V2, out + (size_t)NTOK * U_IN);
}

// round 10
// speedup vs baseline: 2.5821x; 2.5821x over previous
#include <cuda_runtime.h>
#include <cuda_fp16.h>
#include <cstdint>

// Problem constants
#define NTOK      8192          // B*N
#define FDIM      8192          // 2*C*C
#define NCOLS     2560          // 512 + 1024 + 1024
#define U_IN      512
#define EQW       2048

// GEMM tiling (fp16 mma.sync m16n8k16 path; tcgen05 unavailable on this target)
#define TM        128
#define TN        128
#define TKH       64            // K per stage in halves = 128 bytes per row
#define STG       3
#define KT_ITERS  (FDIM / TKH)  // 128

// Scratch (device globals: allocation-free rule)
__device__ __half g_feats[(size_t)NTOK * FDIM];   // 128 MB, fp16 feats
__device__ float  g_wl[(size_t)NTOK * EQW];       // 64 MB, eq activations
__device__ __half g_wtr[(size_t)NCOLS * FDIM];    // 40 MB, W transposed K-major fp16

__device__ __forceinline__ uint32_t smem_u32(const void* p) {
    uint32_t a;
    asm("{ .reg .u64 t; cvta.to.shared.u64 t, %1; cvt.u32.u64 %0, t; }" : "=r"(a) : "l"(p));
    return a;
}

__device__ __forceinline__ void ldsm_x4(uint32_t* r, uint32_t addr) {
    asm volatile("ldmatrix.sync.aligned.m8n8.x4.shared.b16 {%0,%1,%2,%3}, [%4];"
                 : "=r"(r[0]), "=r"(r[1]), "=r"(r[2]), "=r"(r[3]) : "r"(addr));
}

__device__ __forceinline__ void mma_fp16(float* d, const uint32_t* a, uint32_t b0, uint32_t b1) {
    asm volatile("mma.sync.aligned.m16n8k16.row.col.f32.f16.f16.f32 "
                 "{%0,%1,%2,%3}, {%4,%5,%6,%7}, {%8,%9}, {%0,%1,%2,%3};"
                 : "+f"(d[0]), "+f"(d[1]), "+f"(d[2]), "+f"(d[3])
                 : "r"(a[0]), "r"(a[1]), "r"(a[2]), "r"(a[3]), "r"(b0), "r"(b1));
}

// ---------------------------------------------------------------------------
// Kernel 1: feats[tok, h*4096 + i*64 + j] = sum_d t[d,i] * l2norm(u)[d,j]
// j-major store mapping: each warp handles (h, 32 i-rows), lanes = j-pairs,
// so every half2 store is a fully coalesced 128B warp transaction.
// ---------------------------------------------------------------------------
__global__ void feats_kernel(const float* __restrict__ t1, const float* __restrict__ t2,
                             const float* __restrict__ u1, const float* __restrict__ u2) {
    const int tok = blockIdx.x;
    const int tid = threadIdx.x;
    __shared__ float s_t[384];   // [h][d][i] = h*192 + d*64 + i
    __shared__ float s_u[384];

    const size_t base = (size_t)tok * 192;
    for (int idx = tid; idx < 192; idx += 128) {
        s_t[idx]       = t1[base + idx];
        s_t[192 + idx] = t2[base + idx];
        s_u[idx]       = u1[base + idx];
        s_u[192 + idx] = u2[base + idx];
    }
    __syncthreads();

    {   // l2-normalize u columns (axis = D): 128 threads = 128 (h,j) columns
        const int h = tid >> 6, j = tid & 63;
        float* u = s_u + h * 192;
        float a = u[j], b = u[64 + j], c = u[128 + j];
        float inv = rsqrtf(fmaxf(a * a + b * b + c * c, 0.01f));
        u[j] = a * inv; u[64 + j] = b * inv; u[128 + j] = c * inv;
    }
    __syncthreads();

    const int w = tid >> 5, lane = tid & 31;
    const int h = w & 1;
    const int iBase = (w >> 1) * 32;
    const float* uu = s_u + h * 192;
    const float* tt = s_t + h * 192;
    const int j0 = lane * 2;
    const float ua0 = uu[j0],     ub0 = uu[64 + j0],     uc0 = uu[128 + j0];
    const float ua1 = uu[j0 + 1], ub1 = uu[64 + j0 + 1], uc1 = uu[128 + j0 + 1];
    __half* dst = g_feats + (size_t)tok * FDIM + h * 4096 + j0;

    #pragma unroll 8
    for (int ii = 0; ii < 32; ii++) {
        const int i = iBase + ii;
        const float ta = tt[i], tb = tt[64 + i], tc = tt[128 + i];
        float v0 = fmaf(ta, ua0, fmaf(tb, ub0, tc * uc0));
        float v1 = fmaf(ta, ua1, fmaf(tb, ub1, tc * uc1));
        *(__half2*)(dst + (size_t)i * 64) = __floats2half2_rn(v0, v1);
    }
}

// ---------------------------------------------------------------------------
// Kernel 1b: transpose weights into K-major [c][k], fp16
// ---------------------------------------------------------------------------
__global__ void wprep_kernel(const float* __restrict__ Winv, const float* __restrict__ Weq) {
    __shared__ float t[32][33];
    const int bx = blockIdx.x;   // c tile (80)
    const int by = blockIdx.y;   // k tile (256)
    const int tx = threadIdx.x, ty = threadIdx.y;   // 32 x 8

    const int c = bx * 32 + tx;
    const float* src; int col, ld;
    if (c < 512)       { src = Winv;                        col = c;        ld = 512; }
    else if (c < 1536) { src = Weq;                         col = c - 512;  ld = 1024; }
    else               { src = Weq + (size_t)FDIM * 1024;   col = c - 1536; ld = 1024; }

    #pragma unroll
    for (int r = 0; r < 4; r++) {
        int k = by * 32 + ty + r * 8;
        t[ty + r * 8][tx] = src[(size_t)k * ld + col];
    }
    __syncthreads();
    #pragma unroll
    for (int r = 0; r < 4; r++) {
        int cc = bx * 32 + ty + r * 8;
        g_wtr[(size_t)cc * FDIM + by * 32 + tx] = __float2half(t[tx][ty + r * 8]);
    }
}

// ---------------------------------------------------------------------------
// Kernel 2: fp16 mma.sync GEMM, C = feats @ [W_inv|W_eq0|W_eq1], fused BN+ReLU.
// 128x128 CTA tile, K-stage 64, 3-stage cp.async, ldmatrix.x4 fragment loads,
// 8 warps (2x4), warp tile 64x32. XOR-16B swizzle: conflict-free STS + LDSM.
// ---------------------------------------------------------------------------
#define STAGE_BYTES (TM * 128 + TN * 128)    // 32 KB (A 16KB | B 16KB)
#define SMEM_BQ     (TM * 128)
#define SMEM_TOTAL  (STG * STAGE_BYTES + 3 * TN * 4)

__global__ void __launch_bounds__(256, 2) gemm_hmma(
    const float* __restrict__ b_inv, const float* __restrict__ g_inv, const float* __restrict__ be_inv,
    const float* __restrict__ b_eq,  const float* __restrict__ g_eq,  const float* __restrict__ be_eq,
    float* __restrict__ out_invar)
{
    extern __shared__ char smem[];
    const uint32_t sbase = smem_u32(smem);
    const int tid = threadIdx.x;
    const int wid = tid >> 5, lane = tid & 31;
    const int bn = blockIdx.x;            // 0..19 (fast: weight L2 reuse)
    const int bm = blockIdx.y;            // 0..63
    const int colBase = bn * TN;

    float* s_bias = (float*)(smem + STG * STAGE_BYTES);
    float* s_gam  = s_bias + TN;
    float* s_bet  = s_gam + TN;
    if (tid < TN) {
        int c = colBase + tid;
        if (c < 512) { s_bias[tid] = b_inv[c]; s_gam[tid] = g_inv[c]; s_bet[tid] = be_inv[c]; }
        else { int j = c - 512; s_bias[tid] = b_eq[j]; s_gam[tid] = g_eq[j]; s_bet[tid] = be_eq[j]; }
    }

    const __half* Abase = g_feats + (size_t)(bm * TM) * FDIM;
    const __half* Bbase = g_wtr + (size_t)colBase * FDIM;

    auto fill = [&](int kt) {
        const int slot = kt % STG;
        const __half* Ag = Abase + kt * TKH;
        const __half* Bg = Bbase + kt * TKH;
        const uint32_t sA = sbase + slot * STAGE_BYTES;
        const uint32_t sB = sA + SMEM_BQ;
        #pragma unroll
        for (int t = 0; t < 4; t++) {           // 128 rows x 8 chunks of 16B, A and B
            const int id = tid + t * 256;
            const int r = id >> 3, q = id & 7;
            uint32_t off = (uint32_t)(r * 128 + q * 16);
            off ^= (uint32_t)(r & 7) << 4;      // 16B-bank swizzle
            const __half* srcA = Ag + (size_t)r * FDIM + q * 8;
            const __half* srcB = Bg + (size_t)r * FDIM + q * 8;
            asm volatile("cp.async.cg.shared.global [%0], [%1], 16;" :: "r"(sA + off), "l"(srcA));
            asm volatile("cp.async.cg.shared.global [%0], [%1], 16;" :: "r"(sB + off), "l"(srcB));
        }
    };

    const int mBase = (wid >> 2) * 64;
    const int nBase = (wid & 3) * 32;
    const int gID = lane >> 2, tig = lane & 3;
    const int lrow = lane & 15;               // ldmatrix row within 16
    const int khalf = (lane >> 4) & 1;        // ldmatrix k-half select

    float acc[4][4][4];
    #pragma unroll
    for (int a = 0; a < 4; a++)
        #pragma unroll
        for (int b = 0; b < 4; b++)
            #pragma unroll
            for (int c = 0; c < 4; c++) acc[a][b][c] = 0.f;

    auto compute = [&](int slot) {
        const uint32_t sA = sbase + slot * STAGE_BYTES;
        const uint32_t sB = sA + SMEM_BQ;
        #pragma unroll
        for (int kb = 0; kb < 4; kb++) {      // 4 x k16 within the 64-K stage
            const uint32_t kcb = (uint32_t)((kb * 16 + khalf * 8) * 2);
            uint32_t aF[4][4], bF[2][4];
            #pragma unroll
            for (int mt = 0; mt < 4; mt++) {
                const int r = mBase + mt * 16 + lrow;
                uint32_t off = (uint32_t)(r * 128) + kcb;
                off ^= (uint32_t)(r & 7) << 4;
                ldsm_x4(aF[mt], sA + off);
            }
            #pragma unroll
            for (int nt2 = 0; nt2 < 2; nt2++) {
                const int r = nBase + nt2 * 16 + lrow;
                uint32_t off = (uint32_t)(r * 128) + kcb;
                off ^= (uint32_t)(r & 7) << 4;
                ldsm_x4(bF[nt2], sB + off);
            }
            #pragma unroll
            for (int mt = 0; mt < 4; mt++)
                #pragma unroll
                for (int nt = 0; nt < 4; nt++)
                    mma_fp16(acc[mt][nt], aF[mt], bF[nt >> 1][nt & 1], bF[nt >> 1][2 + (nt & 1)]);
        }
    };

    // Prologue
    fill(0); asm volatile("cp.async.commit_group;");
    fill(1); asm volatile("cp.async.commit_group;");

    for (int kt = 0; kt < KT_ITERS; kt++) {
        // Groups committed so far = 2 + kt; allowing 1 pending leaves fill(kt) done.
        asm volatile("cp.async.wait_group 1;");
        __syncthreads();
        if (kt + 2 < KT_ITERS) fill(kt + 2);    // overwrites slot (kt-1)%3: safe post-barrier
        asm volatile("cp.async.commit_group;");  // unconditional: uniform accounting
        compute(kt % STG);
        __syncthreads();
    }

    // Epilogue: bias + inference BN (mean 0, var 1) + ReLU
    const float BNS = 0.99950037468777325f;   // 1/sqrt(1.001)
    const bool isInv = (bn < 4);
    #pragma unroll
    for (int mt = 0; mt < 4; mt++) {
        const int r0 = bm * TM + mBase + mt * 16 + gID;
        #pragma unroll
        for (int nt = 0; nt < 4; nt++) {
            const int cl = nBase + nt * 8 + tig * 2;
            const float ga0 = s_gam[cl] * BNS,   ga1 = s_gam[cl + 1] * BNS;
            const float bi0 = s_bias[cl],        bi1 = s_bias[cl + 1];
            const float be0 = s_bet[cl],         be1 = s_bet[cl + 1];
            float v0 = fmaxf(fmaf(ga0, acc[mt][nt][0] + bi0, be0), 0.f);
            float v1 = fmaxf(fmaf(ga1, acc[mt][nt][1] + bi1, be1), 0.f);
            float v2 = fmaxf(fmaf(ga0, acc[mt][nt][2] + bi0, be0), 0.f);
            float v3 = fmaxf(fmaf(ga1, acc[mt][nt][3] + bi1, be1), 0.f);
            const int c = colBase + cl;
            if (isInv) {
                *(float2*)&out_invar[(size_t)r0 * U_IN + c]       = make_float2(v0, v1);
                *(float2*)&out_invar[(size_t)(r0 + 8) * U_IN + c] = make_float2(v2, v3);
            } else {
                const int cw = c - 512;
                *(float2*)&g_wl[(size_t)r0 * EQW + cw]       = make_float2(v0, v1);
                *(float2*)&g_wl[(size_t)(r0 + 8) * EQW + cw] = make_float2(v2, v3);
            }
        }
    }
}

// ---------------------------------------------------------------------------
// Kernel 3: eqvar[tok, m, l*64+i] = sum_j wl[tok, l*1024 + i*16 + j] * V_l[tok, m, j]
// ---------------------------------------------------------------------------
__global__ void recomb_kernel(const float* __restrict__ V1, const float* __restrict__ V2,
                              float* __restrict__ out_eq) {
    const int tok = blockIdx.x;
    const int tid = threadIdx.x;           // 0..383
    __shared__ float sV[96];               // [l][m][j]
    if (tid < 96) {
        int l = tid / 48, r = tid % 48;
        sV[tid] = (l ? V2 : V1)[(size_t)tok * 48 + r];
    }
    __syncthreads();

    const int m = tid >> 7;
    const int c = tid & 127;
    const int l = c >> 6, i = c & 63;
    const float* w = g_wl + (size_t)tok * EQW + l * 1024 + i * 16;
    const float* v = sV + l * 48 + m * 16;
    float s = 0.f;
    #pragma unroll
    for (int j = 0; j < 16; j++) s = fmaf(w[j], v[j], s);
    out_eq[(size_t)tok * 384 + m * 128 + c] = s;
}

// ---------------------------------------------------------------------------
extern "C" void kernel_launch(void* const* d_in, const int* in_sizes, int n_in,
                              void* d_out, int out_size) {
    const float* t1    = (const float*)d_in[0];
    const float* t2    = (const float*)d_in[1];
    const float* u1    = (const float*)d_in[2];
    const float* u2    = (const float*)d_in[3];
    const float* V1    = (const float*)d_in[4];
    const float* V2    = (const float*)d_in[5];
    const float* W_inv = (const float*)d_in[6];
    const float* b_inv = (const float*)d_in[7];
    const float* g_inv = (const float*)d_in[8];
    const float* be_inv= (const float*)d_in[9];
    const float* W_eq  = (const float*)d_in[10];
    const float* b_eq  = (const float*)d_in[11];
    const float* g_eq  = (const float*)d_in[12];
    const float* be_eq = (const float*)d_in[13];
    float* out = (float*)d_out;

    cudaFuncSetAttribute(gemm_hmma, cudaFuncAttributeMaxDynamicSharedMemorySize, SMEM_TOTAL);

    feats_kernel<<<NTOK, 128>>>(t1, t2, u1, u2);
    wprep_kernel<<<dim3(NCOLS / 32, FDIM / 32), dim3(32, 8)>>>(W_inv, W_eq);
    gemm_hmma<<<dim3(NCOLS / TN, NTOK / TM), 256, SMEM_TOTAL>>>(
        b_inv, g_inv, be_inv, b_eq, g_eq, be_eq, out);
    recomb_kernel<<<NTOK, 384>>>(V1, V2, out + (size_t)NTOK * U_IN);
}